// round 3
// baseline (speedup 1.0000x reference)
#include <cuda_runtime.h>
#include <math.h>

#define NV 3
#define NS 20000
#define NTT 60000
#define NE 800000
#define DD 128
#define RR 6
#define INFEAT 2000
#define SCAN_BLKS 235   // ceil(60000/256)

// ---------------- device scratch (static allocation, allowed) ----------------
__device__ float g_h[(size_t)NTT * DD];             // projected+relu nodes [60000,128]
__device__ float g_xw[(size_t)RR * NTT * DD];       // per-relation transformed nodes
__device__ float g_qn[RR * NTT];
__device__ float g_kn[RR * NTT];
__device__ float g_w6[RR * DD * DD];                // relation weights
__device__ float g_wq[RR * DD];
__device__ float g_wk[RR * DD];
__device__ float g_hout[(size_t)NTT * DD];          // conv output (post relu)
__device__ int   g_cnt[NTT];
__device__ int   g_offs[NTT + 1];
__device__ int   g_cur[NTT];
__device__ int   g_bsum[256];
__device__ int   g_csr[NE];                         // packed src | (type<<20)

// ---------------- CSR build ----------------
__global__ void k_zero_cnt() {
    int i = blockIdx.x * 256 + threadIdx.x;
    if (i < NTT) g_cnt[i] = 0;
}

__global__ void k_count(const int* __restrict__ dst) {
    int e = blockIdx.x * 256 + threadIdx.x;
    if (e < NE) atomicAdd(&g_cnt[dst[e]], 1);
}

__global__ void k_scan1() {
    __shared__ int s[256];
    int i = blockIdx.x * 256 + threadIdx.x;
    s[threadIdx.x] = (i < NTT) ? g_cnt[i] : 0;
    __syncthreads();
    for (int o = 128; o > 0; o >>= 1) {
        if (threadIdx.x < o) s[threadIdx.x] += s[threadIdx.x + o];
        __syncthreads();
    }
    if (threadIdx.x == 0) g_bsum[blockIdx.x] = s[0];
}

__global__ void k_scan2() {
    __shared__ int s[256];
    int t = threadIdx.x;
    int v = (t < SCAN_BLKS) ? g_bsum[t] : 0;
    s[t] = v;
    __syncthreads();
    for (int o = 1; o < 256; o <<= 1) {
        int tmp = (t >= o) ? s[t - o] : 0;
        __syncthreads();
        s[t] += tmp;
        __syncthreads();
    }
    g_bsum[t] = s[t] - v;   // exclusive prefix of block sums
}

__global__ void k_scan3() {
    __shared__ int s[256];
    int t = threadIdx.x;
    int i = blockIdx.x * 256 + t;
    int v = (i < NTT) ? g_cnt[i] : 0;
    s[t] = v;
    __syncthreads();
    for (int o = 1; o < 256; o <<= 1) {
        int tmp = (t >= o) ? s[t - o] : 0;
        __syncthreads();
        s[t] += tmp;
        __syncthreads();
    }
    int excl = s[t] - v + g_bsum[blockIdx.x];
    if (i < NTT) {
        g_offs[i] = excl;
        g_cur[i] = excl;
        if (i == NTT - 1) g_offs[NTT] = excl + v;
    }
}

__global__ void k_scatter(const int* __restrict__ src, const int* __restrict__ dst,
                          const int* __restrict__ typ) {
    int e = blockIdx.x * 256 + threadIdx.x;
    if (e >= NE) return;
    int d = dst[e];
    int pos = atomicAdd(&g_cur[d], 1);
    g_csr[pos] = src[e] | (typ[e] << 20);
}

// ---------------- small weight prep ----------------
__global__ void k_wprep(const float* __restrict__ basis, const float* __restrict__ comp) {
    int idx = blockIdx.x * 256 + threadIdx.x;     // over 6*128*128
    if (idx >= RR * DD * DD) return;
    int r = idx / (DD * DD);
    int rem = idx - r * DD * DD;
    float s = 0.f;
#pragma unroll
    for (int b = 0; b < 4; b++) s += comp[r * 4 + b] * basis[b * DD * DD + rem];
    g_w6[idx] = s;
}

__global__ void k_wqk(const float* __restrict__ att_q, const float* __restrict__ att_k) {
    int idx = blockIdx.x * 256 + threadIdx.x;     // over 6*128 (r,d) pairs
    if (idx >= RR * DD) return;
    const float* row = g_w6 + (size_t)idx * DD;   // w6[r][d][:]
    float sq = 0.f, sk = 0.f;
#pragma unroll 8
    for (int o = 0; o < DD; o++) {
        float v = row[o];
        sq += v * att_q[o];
        sk += v * att_k[o];
    }
    g_wq[idx] = sq;
    g_wk[idx] = sk;
}

// ---------------- per-(relation,node) attention scalars ----------------
__global__ void k_qk() {
    __shared__ float swq[RR * DD], swk[RR * DD];
    for (int i = threadIdx.x; i < RR * DD; i += 256) {
        swq[i] = g_wq[i];
        swk[i] = g_wk[i];
    }
    __syncthreads();
    int warp = threadIdx.x >> 5, lane = threadIdx.x & 31;
    int n = blockIdx.x * 8 + warp;
    if (n >= NTT) return;
    float4 hv = ((const float4*)(g_h + (size_t)n * DD))[lane];
#pragma unroll
    for (int r = 0; r < RR; r++) {
        float4 wqv = ((const float4*)(swq + r * DD))[lane];
        float4 wkv = ((const float4*)(swk + r * DD))[lane];
        float pq = hv.x * wqv.x + hv.y * wqv.y + hv.z * wqv.z + hv.w * wqv.w;
        float pk = hv.x * wkv.x + hv.y * wkv.y + hv.z * wkv.z + hv.w * wkv.w;
        for (int o = 16; o; o >>= 1) {
            pq += __shfl_xor_sync(0xFFFFFFFFu, pq, o);
            pk += __shfl_xor_sync(0xFFFFFFFFu, pk, o);
        }
        if (lane == 0) {
            g_qn[r * NTT + n] = pq;
            g_kn[r * NTT + n] = pk;
        }
    }
}

// ---------------- generic tiled SGEMM: C = A[M,K] x B[K,N(=128)] (+bias)(+relu) ----------------
#define BM 128
#define BN 128
#define BK 16

__global__ __launch_bounds__(256) void k_sgemm(
    const float* __restrict__ A, const float* __restrict__ B,
    const float* __restrict__ bias, float* __restrict__ C,
    int M, int K, long strideB, long strideC, int relu)
{
    const float* Bp = B + (long)blockIdx.z * strideB;
    float* Cp = C + (long)blockIdx.z * strideC;
    int block_m = blockIdx.x * BM;

    __shared__ float As[BK][BM + 4];
    __shared__ float Bs[BK][BN];

    int tid = threadIdx.x;
    int arow = tid >> 2;            // 0..63
    int acol = (tid & 3) * 4;       // 0,4,8,12
    int brow = tid >> 5;            // 0..7
    int bcol = (tid & 31) * 4;      // 0..124

    int ty = tid >> 4, tx = tid & 15;

    float acc[8][8];
#pragma unroll
    for (int m = 0; m < 8; m++)
#pragma unroll
        for (int n = 0; n < 8; n++) acc[m][n] = 0.f;

    for (int k0 = 0; k0 < K; k0 += BK) {
#pragma unroll
        for (int i = 0; i < 2; i++) {
            int r = arow + i * 64;
            int gm = block_m + r;
            float4 v = make_float4(0.f, 0.f, 0.f, 0.f);
            if (gm < M) v = *(const float4*)(A + (long)gm * K + k0 + acol);
            As[acol + 0][r] = v.x;
            As[acol + 1][r] = v.y;
            As[acol + 2][r] = v.z;
            As[acol + 3][r] = v.w;
        }
#pragma unroll
        for (int i = 0; i < 2; i++) {
            int r = brow + i * 8;
            float4 v = *(const float4*)(Bp + (long)(k0 + r) * BN + bcol);
            *(float4*)&Bs[r][bcol] = v;
        }
        __syncthreads();
#pragma unroll
        for (int kk = 0; kk < BK; kk++) {
            float4 a0 = *(const float4*)&As[kk][ty * 8];
            float4 a1 = *(const float4*)&As[kk][ty * 8 + 4];
            float4 b0 = *(const float4*)&Bs[kk][tx * 8];
            float4 b1 = *(const float4*)&Bs[kk][tx * 8 + 4];
            float ra[8] = {a0.x, a0.y, a0.z, a0.w, a1.x, a1.y, a1.z, a1.w};
            float rb[8] = {b0.x, b0.y, b0.z, b0.w, b1.x, b1.y, b1.z, b1.w};
#pragma unroll
            for (int m = 0; m < 8; m++)
#pragma unroll
                for (int n = 0; n < 8; n++) acc[m][n] += ra[m] * rb[n];
        }
        __syncthreads();
    }

#pragma unroll
    for (int m = 0; m < 8; m++) {
        int gm = block_m + ty * 8 + m;
        if (gm >= M) continue;
        float* cp = Cp + (long)gm * BN + tx * 8;
        float v[8];
#pragma unroll
        for (int n = 0; n < 8; n++) {
            float x = acc[m][n];
            if (bias) x += bias[tx * 8 + n];
            if (relu) x = fmaxf(x, 0.f);
            v[n] = x;
        }
        *(float4*)(cp + 0) = make_float4(v[0], v[1], v[2], v[3]);
        *(float4*)(cp + 4) = make_float4(v[4], v[5], v[6], v[7]);
    }
}

// ---------------- warp-per-dst softmax + aggregation ----------------
__global__ void k_aggregate(const float* __restrict__ conv_bias) {
    int warp = threadIdx.x >> 5, lane = threadIdx.x & 31;
    int d = blockIdx.x * 8 + warp;
    if (d >= NTT) return;
    int s = g_offs[d], e1 = g_offs[d + 1];

    // pass 1: max over incoming edges (lane-parallel)
    float m = -INFINITY;
    for (int i = s + lane; i < e1; i += 32) {
        int p = g_csr[i];
        int src = p & 0xFFFFF;
        int t = p >> 20;
        float a = g_qn[t * NTT + d] + g_kn[t * NTT + src];
        a = a > 0.f ? a : 0.2f * a;
        m = fmaxf(m, a);
    }
    for (int o = 16; o; o >>= 1) m = fmaxf(m, __shfl_xor_sync(0xFFFFFFFFu, m, o));

    // pass 2: numerator vector (lanes split feature dim) + denom
    float4 acc = make_float4(0.f, 0.f, 0.f, 0.f);
    float den = 0.f;
    for (int i = s; i < e1; i++) {
        int p = g_csr[i];
        int src = p & 0xFFFFF;
        int t = p >> 20;
        float a = g_qn[t * NTT + d] + g_kn[t * NTT + src];
        a = a > 0.f ? a : 0.2f * a;
        float w = __expf(a - m);
        den += w;
        float4 v = ((const float4*)(g_xw + ((size_t)t * NTT + src) * DD))[lane];
        acc.x += w * v.x;
        acc.y += w * v.y;
        acc.z += w * v.z;
        acc.w += w * v.w;
    }
    float inv = 1.f / (den + 1e-16f);
    float4 b = ((const float4*)conv_bias)[lane];
    float4 o;
    o.x = fmaxf(acc.x * inv + b.x, 0.f);
    o.y = fmaxf(acc.y * inv + b.y, 0.f);
    o.z = fmaxf(acc.z * inv + b.z, 0.f);
    o.w = fmaxf(acc.w * inv + b.w, 0.f);
    ((float4*)(g_hout + (size_t)d * DD))[lane] = o;
}

// ---------------- final linear: [20000,384] @ [384,5] + bias ----------------
__global__ void k_final(const float* __restrict__ w_int, const float* __restrict__ b_int,
                        float* __restrict__ out) {
    int warp = threadIdx.x >> 5, lane = threadIdx.x & 31;
    int n = blockIdx.x * 8 + warp;
    if (n >= NS) return;
    float a0 = 0.f, a1 = 0.f, a2 = 0.f, a3 = 0.f, a4 = 0.f;
    for (int k = lane; k < NV * DD; k += 32) {
        int v = k >> 7, dd = k & 127;
        float f = g_hout[((size_t)(v * NS + n)) * DD + dd];
        const float* wr = w_int + (size_t)k * 5;
        a0 += f * wr[0];
        a1 += f * wr[1];
        a2 += f * wr[2];
        a3 += f * wr[3];
        a4 += f * wr[4];
    }
    for (int o = 16; o; o >>= 1) {
        a0 += __shfl_xor_sync(0xFFFFFFFFu, a0, o);
        a1 += __shfl_xor_sync(0xFFFFFFFFu, a1, o);
        a2 += __shfl_xor_sync(0xFFFFFFFFu, a2, o);
        a3 += __shfl_xor_sync(0xFFFFFFFFu, a3, o);
        a4 += __shfl_xor_sync(0xFFFFFFFFu, a4, o);
    }
    if (lane == 0) {
        float* op = out + (size_t)n * 5;
        op[0] = a0 + b_int[0];
        op[1] = a1 + b_int[1];
        op[2] = a2 + b_int[2];
        op[3] = a3 + b_int[3];
        op[4] = a4 + b_int[4];
    }
}

// ---------------- launch ----------------
extern "C" void kernel_launch(void* const* d_in, const int* in_sizes, int n_in,
                              void* d_out, int out_size) {
    const float* x0   = (const float*)d_in[0];
    const float* wp0  = (const float*)d_in[1];
    const float* bp0  = (const float*)d_in[2];
    const float* x1   = (const float*)d_in[3];
    const float* wp1  = (const float*)d_in[4];
    const float* bp1  = (const float*)d_in[5];
    const float* x2   = (const float*)d_in[6];
    const float* wp2  = (const float*)d_in[7];
    const float* bp2  = (const float*)d_in[8];
    const int*   esrc = (const int*)d_in[9];
    const int*   edst = (const int*)d_in[10];
    const int*   etyp = (const int*)d_in[11];
    const float* basis = (const float*)d_in[12];
    const float* comp  = (const float*)d_in[13];
    const float* attq  = (const float*)d_in[14];
    const float* attk  = (const float*)d_in[15];
    const float* cbias = (const float*)d_in[16];
    const float* wint  = (const float*)d_in[17];
    const float* bint  = (const float*)d_in[18];
    float* out = (float*)d_out;

    float *p_h, *p_xw, *p_w6;
    cudaGetSymbolAddress((void**)&p_h, g_h);
    cudaGetSymbolAddress((void**)&p_xw, g_xw);
    cudaGetSymbolAddress((void**)&p_w6, g_w6);

    // CSR build (independent of GEMMs but serialized on stream — cheap)
    k_zero_cnt<<<SCAN_BLKS, 256>>>();
    k_count<<<NE / 256, 256>>>(edst);
    k_scan1<<<SCAN_BLKS, 256>>>();
    k_scan2<<<1, 256>>>();
    k_scan3<<<SCAN_BLKS, 256>>>();
    k_scatter<<<NE / 256, 256>>>(esrc, edst, etyp);

    // projections -> g_h
    dim3 gp((NS + BM - 1) / BM, 1, 1);
    k_sgemm<<<gp, 256>>>(x0, wp0, bp0, p_h + 0L * NS * DD, NS, INFEAT, 0, 0, 1);
    k_sgemm<<<gp, 256>>>(x1, wp1, bp1, p_h + 1L * NS * DD, NS, INFEAT, 0, 0, 1);
    k_sgemm<<<gp, 256>>>(x2, wp2, bp2, p_h + 2L * NS * DD, NS, INFEAT, 0, 0, 1);

    // relation weights + attention weight vectors
    k_wprep<<<(RR * DD * DD + 255) / 256, 256>>>(basis, comp);
    k_wqk<<<(RR * DD + 255) / 256, 256>>>(attq, attk);

    // xw[r] = h @ w6[r]  (batched over z)
    dim3 gx((NTT + BM - 1) / BM, 1, RR);
    k_sgemm<<<gx, 256>>>(p_h, p_w6, nullptr, p_xw, NTT, DD, (long)DD * DD, (long)NTT * DD, 0);

    // attention scalars per (relation, node)
    k_qk<<<NTT / 8, 256>>>();

    // softmax + aggregation + relu
    k_aggregate<<<NTT / 8, 256>>>(cbias);

    // final classification head
    k_final<<<NS / 8, 256>>>(wint, bint, out);
}

// round 5
// speedup vs baseline: 2.7254x; 2.7254x over previous
#include <cuda_runtime.h>
#include <math.h>
#include <stdint.h>

#define NV 3
#define NS 20000
#define NTT 60000
#define NE 800000
#define DD 128
#define RR 6
#define INFEAT 2000
#define SCAN_BLKS 235   // ceil(60000/256)
#define NW 768          // RR * DD

// ---------------- device scratch ----------------
__device__ float g_h[(size_t)NTT * DD];             // projected+relu nodes [60000,128]
__device__ float g_xwt[(size_t)NTT * NW];           // transformed nodes [node][r*128+o]
__device__ float g_qn[RR * NTT];
__device__ float g_kn[RR * NTT];
__device__ float g_w6t[DD * NW];                    // relation weights [k][r*128+o]
__device__ float g_wq[RR * DD];
__device__ float g_wk[RR * DD];
__device__ float g_hout[(size_t)NTT * DD];          // conv output (post relu)
__device__ int   g_cnt[NTT];
__device__ int   g_offs[NTT + 1];
__device__ int   g_cur[NTT];
__device__ int   g_bsum[256];
__device__ int   g_csr[NE];                         // packed src | (type<<20)

// ---------------- CSR build ----------------
__global__ void k_zero_cnt() {
    int i = blockIdx.x * 256 + threadIdx.x;
    if (i < NTT) g_cnt[i] = 0;
}

__global__ void k_count(const int* __restrict__ dst) {
    int e = blockIdx.x * 256 + threadIdx.x;
    if (e < NE) atomicAdd(&g_cnt[dst[e]], 1);
}

__global__ void k_scan1() {
    __shared__ int s[256];
    int i = blockIdx.x * 256 + threadIdx.x;
    s[threadIdx.x] = (i < NTT) ? g_cnt[i] : 0;
    __syncthreads();
    for (int o = 128; o > 0; o >>= 1) {
        if (threadIdx.x < o) s[threadIdx.x] += s[threadIdx.x + o];
        __syncthreads();
    }
    if (threadIdx.x == 0) g_bsum[blockIdx.x] = s[0];
}

__global__ void k_scan2() {
    __shared__ int s[256];
    int t = threadIdx.x;
    int v = (t < SCAN_BLKS) ? g_bsum[t] : 0;
    s[t] = v;
    __syncthreads();
    for (int o = 1; o < 256; o <<= 1) {
        int tmp = (t >= o) ? s[t - o] : 0;
        __syncthreads();
        s[t] += tmp;
        __syncthreads();
    }
    g_bsum[t] = s[t] - v;   // exclusive prefix of block sums
}

__global__ void k_scan3() {
    __shared__ int s[256];
    int t = threadIdx.x;
    int i = blockIdx.x * 256 + t;
    int v = (i < NTT) ? g_cnt[i] : 0;
    s[t] = v;
    __syncthreads();
    for (int o = 1; o < 256; o <<= 1) {
        int tmp = (t >= o) ? s[t - o] : 0;
        __syncthreads();
        s[t] += tmp;
        __syncthreads();
    }
    int excl = s[t] - v + g_bsum[blockIdx.x];
    if (i < NTT) {
        g_offs[i] = excl;
        g_cur[i] = excl;
        if (i == NTT - 1) g_offs[NTT] = excl + v;
    }
}

__global__ void k_scatter(const int* __restrict__ src, const int* __restrict__ dst,
                          const int* __restrict__ typ) {
    int e = blockIdx.x * 256 + threadIdx.x;
    if (e >= NE) return;
    int d = dst[e];
    int pos = atomicAdd(&g_cur[d], 1);
    g_csr[pos] = src[e] | (typ[e] << 20);
}

// ---------------- small weight prep ----------------
// w6t[k][r*128+o] = sum_b comp[r][b] * basis[b][k][o]
__global__ void k_wprep(const float* __restrict__ basis, const float* __restrict__ comp) {
    int idx = blockIdx.x * 256 + threadIdx.x;     // over 6*128*128
    if (idx >= RR * DD * DD) return;
    int r = idx / (DD * DD);
    int rem = idx - r * DD * DD;
    int d = rem / DD;     // k index
    int o = rem - d * DD;
    float s = 0.f;
#pragma unroll
    for (int b = 0; b < 4; b++) s += comp[r * 4 + b] * basis[b * DD * DD + d * DD + o];
    g_w6t[d * NW + r * DD + o] = s;
}

__global__ void k_wqk(const float* __restrict__ att_q, const float* __restrict__ att_k) {
    int idx = blockIdx.x * 256 + threadIdx.x;     // over 6*128 (r,d) pairs
    if (idx >= RR * DD) return;
    int r = idx / DD, d = idx - r * DD;
    const float* row = g_w6t + d * NW + r * DD;   // w6[r][d][:]
    float sq = 0.f, sk = 0.f;
#pragma unroll 8
    for (int o = 0; o < DD; o++) {
        float v = row[o];
        sq += v * att_q[o];
        sk += v * att_k[o];
    }
    g_wq[idx] = sq;
    g_wk[idx] = sk;
}

// ---------------- per-(relation,node) attention scalars ----------------
__global__ void k_qk() {
    __shared__ float swq[RR * DD], swk[RR * DD];
    for (int i = threadIdx.x; i < RR * DD; i += 256) {
        swq[i] = g_wq[i];
        swk[i] = g_wk[i];
    }
    __syncthreads();
    int warp = threadIdx.x >> 5, lane = threadIdx.x & 31;
    int n = blockIdx.x * 8 + warp;
    if (n >= NTT) return;
    float4 hv = ((const float4*)(g_h + (size_t)n * DD))[lane];
#pragma unroll
    for (int r = 0; r < RR; r++) {
        float4 wqv = ((const float4*)(swq + r * DD))[lane];
        float4 wkv = ((const float4*)(swk + r * DD))[lane];
        float pq = hv.x * wqv.x + hv.y * wqv.y + hv.z * wqv.z + hv.w * wqv.w;
        float pk = hv.x * wkv.x + hv.y * wkv.y + hv.z * wkv.z + hv.w * wkv.w;
        for (int o = 16; o; o >>= 1) {
            pq += __shfl_xor_sync(0xFFFFFFFFu, pq, o);
            pk += __shfl_xor_sync(0xFFFFFFFFu, pk, o);
        }
        if (lane == 0) {
            g_qn[r * NTT + n] = pq;
            g_kn[r * NTT + n] = pk;
        }
    }
}

// ---------------- TF32 mma GEMM: C[M,*] = A[M,K] x B[K,N], 128x128 tiles ----------------
#define PADA 20    // stride 20 -> conflict-free A fragment reads
#define PADB 136   // stride 136 (== 8 mod 32) -> conflict-free B fragment reads

__device__ __forceinline__ float tf32r(float x) {
    uint32_t u;
    asm("cvt.rna.tf32.f32 %0, %1;" : "=r"(u) : "f"(x));
    return __uint_as_float(u);
}

__device__ __forceinline__ void mma_tf32(float* c, const uint32_t* a, const uint32_t* b) {
    asm volatile(
        "mma.sync.aligned.m16n8k8.row.col.f32.tf32.tf32.f32 "
        "{%0,%1,%2,%3}, {%4,%5,%6,%7}, {%8,%9}, {%0,%1,%2,%3};\n"
        : "+f"(c[0]), "+f"(c[1]), "+f"(c[2]), "+f"(c[3])
        : "r"(a[0]), "r"(a[1]), "r"(a[2]), "r"(a[3]), "r"(b[0]), "r"(b[1]));
}

// 256 threads, 8 warps: warp grid 2(M) x 4(N); warp tile 64x32 = 4x4 m16n8 mma tiles.
__device__ __forceinline__ void mma_tile(
    const float* __restrict__ A, int lda,
    const float* __restrict__ B, int ldb,
    const float* __restrict__ bias,
    float* __restrict__ C, int ldc,
    int M, int m0, int n0, int K, int relu)
{
    __shared__ float As[128][PADA];   // [m][k]
    __shared__ float Bs[16][PADB];    // [k][n]

    int tid = threadIdx.x;
    int lane = tid & 31, wid = tid >> 5;
    int wm = (wid & 1) * 64, wn = (wid >> 1) * 32;
    int tr = lane >> 2, tc = lane & 3;

    int ar = tid >> 1, ak = (tid & 1) * 8;       // A load: row 0..127, k-octet
    int br = tid >> 4, bn = (tid & 15) * 8;      // B load: k-row 0..15, n-octet

    float acc[4][4][4];
#pragma unroll
    for (int mt = 0; mt < 4; mt++)
#pragma unroll
        for (int nt = 0; nt < 4; nt++)
#pragma unroll
            for (int i = 0; i < 4; i++) acc[mt][nt][i] = 0.f;

    float4 pa0, pa1, pb0, pb1;
    bool arow_ok = (m0 + ar < M);

    // prefetch first tile
    {
        if (arow_ok) {
            const float* p = A + (long)(m0 + ar) * lda + ak;
            pa0 = *(const float4*)p;
            pa1 = *(const float4*)(p + 4);
        } else pa0 = pa1 = make_float4(0.f, 0.f, 0.f, 0.f);
        const float* q = B + (long)br * ldb + n0 + bn;
        pb0 = *(const float4*)q;
        pb1 = *(const float4*)(q + 4);
    }
    // store first tile (tf32-rounded)
    {
        float* pA = &As[ar][ak];
        pA[0] = tf32r(pa0.x); pA[1] = tf32r(pa0.y); pA[2] = tf32r(pa0.z); pA[3] = tf32r(pa0.w);
        pA[4] = tf32r(pa1.x); pA[5] = tf32r(pa1.y); pA[6] = tf32r(pa1.z); pA[7] = tf32r(pa1.w);
        float* pB = &Bs[br][bn];
        pB[0] = tf32r(pb0.x); pB[1] = tf32r(pb0.y); pB[2] = tf32r(pb0.z); pB[3] = tf32r(pb0.w);
        pB[4] = tf32r(pb1.x); pB[5] = tf32r(pb1.y); pB[6] = tf32r(pb1.z); pB[7] = tf32r(pb1.w);
    }
    __syncthreads();

    int nk = K >> 4;
    for (int it = 0; it < nk; it++) {
        bool more = (it + 1 < nk);
        if (more) {
            int k0 = (it + 1) << 4;
            if (arow_ok) {
                const float* p = A + (long)(m0 + ar) * lda + k0 + ak;
                pa0 = *(const float4*)p;
                pa1 = *(const float4*)(p + 4);
            } else pa0 = pa1 = make_float4(0.f, 0.f, 0.f, 0.f);
            const float* q = B + (long)(k0 + br) * ldb + n0 + bn;
            pb0 = *(const float4*)q;
            pb1 = *(const float4*)(q + 4);
        }

#pragma unroll
        for (int ks = 0; ks < 2; ks++) {
            int kb = ks * 8;
            uint32_t a[4][4], b[4][2];
#pragma unroll
            for (int mt = 0; mt < 4; mt++) {
                int m = wm + mt * 16;
                a[mt][0] = __float_as_uint(As[m + tr    ][kb + tc    ]);
                a[mt][1] = __float_as_uint(As[m + tr + 8][kb + tc    ]);
                a[mt][2] = __float_as_uint(As[m + tr    ][kb + tc + 4]);
                a[mt][3] = __float_as_uint(As[m + tr + 8][kb + tc + 4]);
            }
#pragma unroll
            for (int nt = 0; nt < 4; nt++) {
                int n = wn + nt * 8;
                b[nt][0] = __float_as_uint(Bs[kb + tc    ][n + tr]);
                b[nt][1] = __float_as_uint(Bs[kb + tc + 4][n + tr]);
            }
#pragma unroll
            for (int mt = 0; mt < 4; mt++)
#pragma unroll
                for (int nt = 0; nt < 4; nt++)
                    mma_tf32(acc[mt][nt], a[mt], b[nt]);
        }

        if (more) {
            __syncthreads();
            float* pA = &As[ar][ak];
            pA[0] = tf32r(pa0.x); pA[1] = tf32r(pa0.y); pA[2] = tf32r(pa0.z); pA[3] = tf32r(pa0.w);
            pA[4] = tf32r(pa1.x); pA[5] = tf32r(pa1.y); pA[6] = tf32r(pa1.z); pA[7] = tf32r(pa1.w);
            float* pB = &Bs[br][bn];
            pB[0] = tf32r(pb0.x); pB[1] = tf32r(pb0.y); pB[2] = tf32r(pb0.z); pB[3] = tf32r(pb0.w);
            pB[4] = tf32r(pb1.x); pB[5] = tf32r(pb1.y); pB[6] = tf32r(pb1.z); pB[7] = tf32r(pb1.w);
            __syncthreads();
        }
    }

    // epilogue
#pragma unroll
    for (int mt = 0; mt < 4; mt++) {
#pragma unroll
        for (int half = 0; half < 2; half++) {
            int lrow = wm + mt * 16 + tr + half * 8;
            int grow = m0 + lrow;
            if (grow >= M) continue;
#pragma unroll
            for (int nt = 0; nt < 4; nt++) {
                int lcol = wn + nt * 8 + tc * 2;
                float v0 = acc[mt][nt][half * 2 + 0];
                float v1 = acc[mt][nt][half * 2 + 1];
                if (bias) { v0 += bias[lcol]; v1 += bias[lcol + 1]; }
                if (relu) { v0 = fmaxf(v0, 0.f); v1 = fmaxf(v1, 0.f); }
                *(float2*)(C + (long)grow * ldc + n0 + lcol) = make_float2(v0, v1);
            }
        }
    }
}

#define PROJ_TPB 157   // ceil(20000/128) tiles per view

__global__ __launch_bounds__(256) void k_proj_mma(
    const float* __restrict__ x0, const float* __restrict__ x1, const float* __restrict__ x2,
    const float* __restrict__ w0, const float* __restrict__ w1, const float* __restrict__ w2,
    const float* __restrict__ b0, const float* __restrict__ b1, const float* __restrict__ b2)
{
    int t = blockIdx.x;
    int v = t / PROJ_TPB, lm = t - v * PROJ_TPB;
    const float* A = (v == 0) ? x0 : (v == 1) ? x1 : x2;
    const float* W = (v == 0) ? w0 : (v == 1) ? w1 : w2;
    const float* bi = (v == 0) ? b0 : (v == 1) ? b1 : b2;
    mma_tile(A, INFEAT, W, DD, bi, g_h + (long)v * NS * DD, DD,
             NS, lm * 128, 0, INFEAT, 1);
}

__global__ __launch_bounds__(256) void k_xw_mma() {
    mma_tile(g_h, DD, g_w6t, NW, nullptr, g_xwt, NW,
             NTT, blockIdx.x * 128, blockIdx.y * 128, DD, 0);
}

// ---------------- warp-per-dst softmax + aggregation ----------------
__global__ void k_aggregate(const float* __restrict__ conv_bias) {
    int warp = threadIdx.x >> 5, lane = threadIdx.x & 31;
    int d = blockIdx.x * 8 + warp;
    if (d >= NTT) return;
    int s = g_offs[d], e1 = g_offs[d + 1];

    // pass 1: max over incoming edges (lane-parallel)
    float m = -INFINITY;
    for (int i = s + lane; i < e1; i += 32) {
        int p = g_csr[i];
        int src = p & 0xFFFFF;
        int t = p >> 20;
        float a = g_qn[t * NTT + d] + g_kn[t * NTT + src];
        a = a > 0.f ? a : 0.2f * a;
        m = fmaxf(m, a);
    }
    for (int o = 16; o; o >>= 1) m = fmaxf(m, __shfl_xor_sync(0xFFFFFFFFu, m, o));

    // pass 2: numerator vector (lanes split feature dim) + denom
    float4 acc = make_float4(0.f, 0.f, 0.f, 0.f);
    float den = 0.f;
    for (int i = s; i < e1; i++) {
        int p = g_csr[i];
        int src = p & 0xFFFFF;
        int t = p >> 20;
        float a = g_qn[t * NTT + d] + g_kn[t * NTT + src];
        a = a > 0.f ? a : 0.2f * a;
        float w = __expf(a - m);
        den += w;
        float4 v = ((const float4*)(g_xwt + (size_t)src * NW + t * DD))[lane];
        acc.x += w * v.x;
        acc.y += w * v.y;
        acc.z += w * v.z;
        acc.w += w * v.w;
    }
    float inv = 1.f / (den + 1e-16f);
    float4 b = ((const float4*)conv_bias)[lane];
    float4 o;
    o.x = fmaxf(acc.x * inv + b.x, 0.f);
    o.y = fmaxf(acc.y * inv + b.y, 0.f);
    o.z = fmaxf(acc.z * inv + b.z, 0.f);
    o.w = fmaxf(acc.w * inv + b.w, 0.f);
    ((float4*)(g_hout + (size_t)d * DD))[lane] = o;
}

// ---------------- final linear: [20000,384] @ [384,5] + bias ----------------
__global__ void k_final(const float* __restrict__ w_int, const float* __restrict__ b_int,
                        float* __restrict__ out) {
    int warp = threadIdx.x >> 5, lane = threadIdx.x & 31;
    int n = blockIdx.x * 8 + warp;
    if (n >= NS) return;
    float a0 = 0.f, a1 = 0.f, a2 = 0.f, a3 = 0.f, a4 = 0.f;
    for (int k = lane; k < NV * DD; k += 32) {
        int v = k >> 7, dd = k & 127;
        float f = g_hout[((size_t)(v * NS + n)) * DD + dd];
        const float* wr = w_int + (size_t)k * 5;
        a0 += f * wr[0];
        a1 += f * wr[1];
        a2 += f * wr[2];
        a3 += f * wr[3];
        a4 += f * wr[4];
    }
    for (int o = 16; o; o >>= 1) {
        a0 += __shfl_xor_sync(0xFFFFFFFFu, a0, o);
        a1 += __shfl_xor_sync(0xFFFFFFFFu, a1, o);
        a2 += __shfl_xor_sync(0xFFFFFFFFu, a2, o);
        a3 += __shfl_xor_sync(0xFFFFFFFFu, a3, o);
        a4 += __shfl_xor_sync(0xFFFFFFFFu, a4, o);
    }
    if (lane == 0) {
        float* op = out + (size_t)n * 5;
        op[0] = a0 + b_int[0];
        op[1] = a1 + b_int[1];
        op[2] = a2 + b_int[2];
        op[3] = a3 + b_int[3];
        op[4] = a4 + b_int[4];
    }
}

// ---------------- launch ----------------
extern "C" void kernel_launch(void* const* d_in, const int* in_sizes, int n_in,
                              void* d_out, int out_size) {
    const float* x0   = (const float*)d_in[0];
    const float* wp0  = (const float*)d_in[1];
    const float* bp0  = (const float*)d_in[2];
    const float* x1   = (const float*)d_in[3];
    const float* wp1  = (const float*)d_in[4];
    const float* bp1  = (const float*)d_in[5];
    const float* x2   = (const float*)d_in[6];
    const float* wp2  = (const float*)d_in[7];
    const float* bp2  = (const float*)d_in[8];
    const int*   esrc = (const int*)d_in[9];
    const int*   edst = (const int*)d_in[10];
    const int*   etyp = (const int*)d_in[11];
    const float* basis = (const float*)d_in[12];
    const float* comp  = (const float*)d_in[13];
    const float* attq  = (const float*)d_in[14];
    const float* attk  = (const float*)d_in[15];
    const float* cbias = (const float*)d_in[16];
    const float* wint  = (const float*)d_in[17];
    const float* bint  = (const float*)d_in[18];
    float* out = (float*)d_out;

    // CSR build
    k_zero_cnt<<<SCAN_BLKS, 256>>>();
    k_count<<<NE / 256, 256>>>(edst);
    k_scan1<<<SCAN_BLKS, 256>>>();
    k_scan2<<<1, 256>>>();
    k_scan3<<<SCAN_BLKS, 256>>>();
    k_scatter<<<NE / 256, 256>>>(esrc, edst, etyp);

    // projections (tf32 tensor core), all 3 views in one launch
    k_proj_mma<<<NV * PROJ_TPB, 256>>>(x0, x1, x2, wp0, wp1, wp2, bp0, bp1, bp2);

    // relation weights (transposed layout) + attention weight vectors
    k_wprep<<<(RR * DD * DD + 255) / 256, 256>>>(basis, comp);
    k_wqk<<<(RR * DD + 255) / 256, 256>>>(attq, attk);

    // xwt = h @ w6t : [60000,128] x [128,768]
    dim3 gx((NTT + 127) / 128, RR);
    k_xw_mma<<<gx, 256>>>();

    // attention scalars per (relation, node)
    k_qk<<<NTT / 8, 256>>>();

    // softmax + aggregation + relu
    k_aggregate<<<NTT / 8, 256>>>(cbias);

    // final classification head
    k_final<<<NS / 8, 256>>>(wint, bint, out);
}